// round 1
// baseline (speedup 1.0000x reference)
#include <cuda_runtime.h>
#include <math.h>

// ---------------- problem constants ----------------
#define B_    2
#define S_    2048
#define DIM_  2048
#define H_    16
#define NOPE_ 128
#define ROPE_ 64
#define QKH_  192          // NOPE + ROPE
#define KVR_  512
#define VD_   128
#define DQK_  576          // KVR + ROPE
#define BS_   (B_*S_)      // 4096
#define NQ_   (H_*QKH_)    // 3072

static const float SCALE_F = 0.07216878364870323f;   // 192^-0.5

// ---------------- scratch (device globals; no allocs allowed) ----------------
__device__ float g_q_raw [(size_t)BS_*NQ_];          // 4096 x 3072   (50 MB)
__device__ float g_kv_raw[(size_t)BS_*DQK_];         // 4096 x 576
__device__ float g_kfull [(size_t)BS_*DQK_];         // [kv_cache(512) | k_pe(64)]
__device__ float g_qfull [(size_t)BS_*H_*DQK_];      // [q_lat(512) | q_pe(64)]  (151 MB)
__device__ float g_scores[(size_t)B_*H_*S_*S_];      // 32 x 2048 x 2048 (537 MB), reused as attn
__device__ float g_outlat[(size_t)BS_*H_*KVR_];      // 4096 x 16 x 512  (134 MB)
__device__ float g_outv  [(size_t)BS_*H_*VD_];       // 4096 x 2048
__device__ float g_cos   [S_*(ROPE_/2)];
__device__ float g_sin   [S_*(ROPE_/2)];

// ---------------- RoPE tables (double precision angle/cos) ----------------
__global__ void rope_init_kernel() {
    int idx = blockIdx.x*blockDim.x + threadIdx.x;
    if (idx >= S_*(ROPE_/2)) return;
    int t = idx / (ROPE_/2);
    int i = idx % (ROPE_/2);
    double freq = pow(10000.0, -(double)(2*i)/(double)ROPE_);
    double ang  = (double)t * freq;
    g_cos[idx] = (float)cos(ang);
    g_sin[idx] = (float)sin(ang);
}

// ---------------- rmsnorm(kv_lat) + RoPE(k_pe, q_pe) ----------------
__global__ void __launch_bounds__(256) prep_kernel(const float* __restrict__ kv_norm_w) {
    int bs  = blockIdx.x;            // 0..4095
    int s   = bs % S_;
    int tid = threadIdx.x;
    const float* kv = g_kv_raw + (size_t)bs*DQK_;
    float*       kf = g_kfull  + (size_t)bs*DQK_;

    __shared__ float red[256];
    float ss = 0.f;
    for (int j = tid; j < KVR_; j += 256) { float v = kv[j]; ss += v*v; }
    red[tid] = ss; __syncthreads();
    #pragma unroll
    for (int o = 128; o > 0; o >>= 1) {
        if (tid < o) red[tid] += red[tid+o];
        __syncthreads();
    }
    float inv = 1.f / sqrtf(red[0] / (float)KVR_ + 1e-6f);

    for (int j = tid; j < KVR_; j += 256)
        kf[j] = kv[j] * inv * kv_norm_w[j];

    // k_pe rope (32 pairs)
    for (int i = tid; i < ROPE_/2; i += 256) {
        float x0 = kv[KVR_ + 2*i], x1 = kv[KVR_ + 2*i + 1];
        float c = g_cos[s*(ROPE_/2)+i], sn = g_sin[s*(ROPE_/2)+i];
        kf[KVR_ + 2*i]     = x0*c  - x1*sn;
        kf[KVR_ + 2*i + 1] = x0*sn + x1*c;
    }

    // q_pe rope: 16 heads * 32 pairs
    const float* qr = g_q_raw + (size_t)bs*NQ_;
    float*       qf = g_qfull + (size_t)bs*H_*DQK_;
    for (int idx = tid; idx < H_*(ROPE_/2); idx += 256) {
        int h = idx >> 5, i = idx & 31;
        float x0 = qr[h*QKH_ + NOPE_ + 2*i], x1 = qr[h*QKH_ + NOPE_ + 2*i + 1];
        float c = g_cos[s*(ROPE_/2)+i], sn = g_sin[s*(ROPE_/2)+i];
        qf[h*DQK_ + KVR_ + 2*i]     = x0*c  - x1*sn;
        qf[h*DQK_ + KVR_ + 2*i + 1] = x0*sn + x1*c;
    }
}

// ---------------- generic batched tiled SGEMM: C = A * op(B) ----------------
// A: [M,K] row-major (lda). B: TRANS_B ? [N,K] : [K,N] (ldb). C: [M,N] (ldc).
// Batch z offsets: ptr += (z/div)*s1 + (z%div)*s2.
// CSKIP: skip tiles fully above the causal diagonal (scores GEMM).
// CKLIM: clamp K to end of this row tile (attn@V GEMM; attn rows are zero past s).
template<bool TRANS_B, bool CSKIP, bool CKLIM>
__global__ void __launch_bounds__(256) gemm_kernel(
    const float* __restrict__ A, const float* __restrict__ Bm, float* __restrict__ C,
    int M, int N, int K, int lda, int ldb, int ldc,
    int divA, long long sA1, long long sA2,
    int divB, long long sB1, long long sB2,
    int divC, long long sC1, long long sC2)
{
    constexpr int BM = 64, BN = 64, BK = 16;
    int z = blockIdx.z;
    A  += (long long)(z/divA)*sA1 + (long long)(z%divA)*sA2;
    Bm += (long long)(z/divB)*sB1 + (long long)(z%divB)*sB2;
    C  += (long long)(z/divC)*sC1 + (long long)(z%divC)*sC2;

    int m0 = blockIdx.y*BM, n0 = blockIdx.x*BN;
    if (CSKIP && n0 >= m0 + BM) return;
    int kEnd = CKLIM ? min(K, m0 + BM) : K;

    __shared__ float As[BK][BM];
    __shared__ float Bs[BK][BN];

    int tx = threadIdx.x, ty = threadIdx.y;
    int tid = ty*16 + tx;
    float acc[4][4] = {};

    for (int k0 = 0; k0 < kEnd; k0 += BK) {
        #pragma unroll
        for (int i = 0; i < 4; i++) {
            int idx = tid + i*256;
            int r = idx >> 4, c = idx & 15;
            As[c][r] = A[(size_t)(m0+r)*lda + (k0+c)];
        }
        if (TRANS_B) {
            #pragma unroll
            for (int i = 0; i < 4; i++) {
                int idx = tid + i*256;
                int r = idx >> 4, c = idx & 15;
                Bs[c][r] = Bm[(size_t)(n0+r)*ldb + (k0+c)];
            }
        } else {
            #pragma unroll
            for (int i = 0; i < 4; i++) {
                int idx = tid + i*256;
                int kk = idx >> 6, nn = idx & 63;
                Bs[kk][nn] = Bm[(size_t)(k0+kk)*ldb + (n0+nn)];
            }
        }
        __syncthreads();

        #pragma unroll
        for (int k = 0; k < BK; k++) {
            float4 av = *reinterpret_cast<const float4*>(&As[k][ty*4]);
            float4 bv = *reinterpret_cast<const float4*>(&Bs[k][tx*4]);
            float a0=av.x,a1=av.y,a2=av.z,a3=av.w;
            float b0=bv.x,b1=bv.y,b2=bv.z,b3=bv.w;
            acc[0][0]+=a0*b0; acc[0][1]+=a0*b1; acc[0][2]+=a0*b2; acc[0][3]+=a0*b3;
            acc[1][0]+=a1*b0; acc[1][1]+=a1*b1; acc[1][2]+=a1*b2; acc[1][3]+=a1*b3;
            acc[2][0]+=a2*b0; acc[2][1]+=a2*b1; acc[2][2]+=a2*b2; acc[2][3]+=a2*b3;
            acc[3][0]+=a3*b0; acc[3][1]+=a3*b1; acc[3][2]+=a3*b2; acc[3][3]+=a3*b3;
        }
        __syncthreads();
    }

    #pragma unroll
    for (int i = 0; i < 4; i++) {
        size_t row = (size_t)(m0 + ty*4 + i);
        #pragma unroll
        for (int j = 0; j < 4; j++)
            C[row*ldc + n0 + tx*4 + j] = acc[i][j];
    }
}

// ---------------- causal softmax, in-place on g_scores ----------------
__global__ void __launch_bounds__(256) softmax_kernel() {
    int s = blockIdx.x;         // query position within batch
    int z = blockIdx.y;         // b*H + h
    float* row = g_scores + ((size_t)z*S_ + s)*S_;
    int n = s + 1;
    int tid = threadIdx.x;
    __shared__ float red[256];

    float mx = -3.4e38f;
    for (int t = tid; t < n; t += 256) mx = fmaxf(mx, row[t]);
    red[tid] = mx; __syncthreads();
    #pragma unroll
    for (int o = 128; o > 0; o >>= 1) {
        if (tid < o) red[tid] = fmaxf(red[tid], red[tid+o]);
        __syncthreads();
    }
    mx = red[0];
    __syncthreads();

    float sum = 0.f;
    for (int t = tid; t < n; t += 256) {
        float e = expf((row[t] - mx) * SCALE_F);
        row[t] = e;
        sum += e;
    }
    red[tid] = sum; __syncthreads();
    #pragma unroll
    for (int o = 128; o > 0; o >>= 1) {
        if (tid < o) red[tid] += red[tid+o];
        __syncthreads();
    }
    float inv = 1.f / red[0];

    for (int t = tid; t < n; t += 256) row[t] *= inv;
    for (int t = n + tid; t < S_; t += 256) row[t] = 0.f;   // valid zeros for CKLIM PV gemm
}

// ---------------- launch ----------------
extern "C" void kernel_launch(void* const* d_in, const int* in_sizes, int n_in,
                              void* d_out, int out_size) {
    const float* x      = (const float*)d_in[0];
    const float* wq     = (const float*)d_in[1];
    const float* wkv_a  = (const float*)d_in[2];
    const float* wkv_b  = (const float*)d_in[3];
    const float* wo     = (const float*)d_in[4];
    const float* kvw    = (const float*)d_in[5];
    float* out = (float*)d_out;

    float *q_raw, *kv_raw, *kfull, *qfull, *scores, *outlat, *outv;
    cudaGetSymbolAddress((void**)&q_raw,  g_q_raw);
    cudaGetSymbolAddress((void**)&kv_raw, g_kv_raw);
    cudaGetSymbolAddress((void**)&kfull,  g_kfull);
    cudaGetSymbolAddress((void**)&qfull,  g_qfull);
    cudaGetSymbolAddress((void**)&scores, g_scores);
    cudaGetSymbolAddress((void**)&outlat, g_outlat);
    cudaGetSymbolAddress((void**)&outv,   g_outv);

    dim3 blk(16,16);

    // 1) q_raw = x @ wq^T            [4096,3072] = [4096,2048]*[3072,2048]^T
    gemm_kernel<true,false,false><<<dim3(NQ_/64, BS_/64, 1), blk>>>(
        x, wq, q_raw, BS_, NQ_, DIM_, DIM_, DIM_, NQ_,
        1,0,0, 1,0,0, 1,0,0);

    // 2) kv_raw = x @ wkv_a^T        [4096,576]
    gemm_kernel<true,false,false><<<dim3(DQK_/64, BS_/64, 1), blk>>>(
        x, wkv_a, kv_raw, BS_, DQK_, DIM_, DIM_, DIM_, DQK_,
        1,0,0, 1,0,0, 1,0,0);

    // 3) RoPE tables
    rope_init_kernel<<<(S_*(ROPE_/2)+255)/256, 256>>>();

    // 4) rmsnorm + rope -> g_kfull, g_qfull[:,512:576]
    prep_kernel<<<BS_, 256>>>(kvw);

    // 5) q_lat[h] = q_nope[:,h] @ wkv_b_h[h,:128,:]   (z = head)
    gemm_kernel<false,false,false><<<dim3(KVR_/64, BS_/64, H_), blk>>>(
        q_raw, wkv_b, qfull, BS_, KVR_, NOPE_, NQ_, KVR_, H_*DQK_,
        1, QKH_, 0,
        1, (long long)(NOPE_+VD_)*KVR_, 0,
        1, DQK_, 0);

    // 6) scores[b,h] = q_full[b,:,h,:] @ k_full[b]^T  (z = b*H+h), causal tile skip
    gemm_kernel<true,true,false><<<dim3(S_/64, S_/64, B_*H_), blk>>>(
        qfull, kfull, scores, S_, S_, DQK_, H_*DQK_, DQK_, S_,
        H_, (long long)S_*H_*DQK_, DQK_,
        H_, (long long)S_*DQK_, 0,
        1, (long long)S_*S_, 0);

    // 7) causal softmax in-place
    softmax_kernel<<<dim3(S_, B_*H_), 256>>>();

    // 8) out_lat[b,:,h,:] = attn[b,h] @ kv_cache[b]   causal K-limit
    gemm_kernel<false,false,true><<<dim3(KVR_/64, S_/64, B_*H_), blk>>>(
        scores, kfull, outlat, S_, KVR_, S_, S_, DQK_, H_*KVR_,
        1, (long long)S_*S_, 0,
        H_, (long long)S_*DQK_, 0,
        H_, (long long)S_*H_*KVR_, KVR_);

    // 9) outv[:,h*128:] = out_lat[:,h,:] @ wkv_b_h[h,128:,:]^T  (z = head)
    gemm_kernel<true,false,false><<<dim3(VD_/64, BS_/64, H_), blk>>>(
        outlat, wkv_b + (size_t)NOPE_*KVR_, outv, BS_, VD_, KVR_, H_*KVR_, KVR_, H_*VD_,
        1, KVR_, 0,
        1, (long long)(NOPE_+VD_)*KVR_, 0,
        1, VD_, 0);

    // 10) out = outv @ wo^T          [4096,2048]
    gemm_kernel<true,false,false><<<dim3(DIM_/64, BS_/64, 1), blk>>>(
        outv, wo, out, BS_, DIM_, H_*VD_, H_*VD_, H_*VD_, DIM_,
        1,0,0, 1,0,0, 1,0,0);
}

// round 3
// speedup vs baseline: 4.3259x; 4.3259x over previous
#include <cuda_runtime.h>
#include <cuda_bf16.h>
#include <math.h>
#include <stdint.h>

// ---------------- problem constants ----------------
#define B_    2
#define S_    2048
#define DIM_  2048
#define H_    16
#define NOPE_ 128
#define ROPE_ 64
#define QKH_  192          // NOPE + ROPE
#define KVR_  512
#define VD_   128
#define DQK_  576          // KVR + ROPE
#define BS_   (B_*S_)      // 4096
#define NQ_   (H_*QKH_)    // 3072

static const float SCALE_F = 0.07216878364870323f;   // 192^-0.5

// ---------------- scratch (device globals; no allocs allowed) ----------------
__device__ float g_q_raw [(size_t)BS_*NQ_];
__device__ float g_kv_raw[(size_t)BS_*DQK_];
__device__ float g_kfull [(size_t)BS_*DQK_];
__device__ float g_qfull [(size_t)BS_*H_*DQK_];
__device__ float g_scores[(size_t)B_*H_*S_*S_];
__device__ float g_outlat[(size_t)BS_*H_*KVR_];
__device__ float g_outv  [(size_t)BS_*H_*VD_];
__device__ float g_cos   [S_*(ROPE_/2)];
__device__ float g_sin   [S_*(ROPE_/2)];

// ---------------- helpers ----------------
__device__ __forceinline__ uint32_t smem_u32(const void* p){
    uint32_t a;
    asm("{ .reg .u64 t; cvta.to.shared.u64 t, %1; cvt.u32.u64 %0, t; }" : "=r"(a) : "l"(p));
    return a;
}
// hi = truncated bf16 pair (x low half, y high half); lo = rn(x - hi)
__device__ __forceinline__ void split2(float x, float y, uint32_t& h, uint32_t& l){
    uint32_t xb = __float_as_uint(x), yb = __float_as_uint(y);
    h = __byte_perm(xb, yb, 0x7632);
    float xh = __uint_as_float(xb & 0xFFFF0000u);
    float yh = __uint_as_float(yb & 0xFFFF0000u);
    __nv_bfloat162 lb = __floats2bfloat162_rn(x - xh, y - yh);
    l = *reinterpret_cast<uint32_t*>(&lb);
}
__device__ __forceinline__ void ldm_x4(uint32_t* r, uint32_t addr){
    asm volatile("ldmatrix.sync.aligned.m8n8.x4.shared.b16 {%0,%1,%2,%3}, [%4];"
        : "=r"(r[0]),"=r"(r[1]),"=r"(r[2]),"=r"(r[3]) : "r"(addr));
}
__device__ __forceinline__ void ldm_x2(uint32_t* r, uint32_t addr){
    asm volatile("ldmatrix.sync.aligned.m8n8.x2.shared.b16 {%0,%1}, [%2];"
        : "=r"(r[0]),"=r"(r[1]) : "r"(addr));
}
__device__ __forceinline__ void ldm_x2t(uint32_t* r, uint32_t addr){
    asm volatile("ldmatrix.sync.aligned.m8n8.x2.trans.shared.b16 {%0,%1}, [%2];"
        : "=r"(r[0]),"=r"(r[1]) : "r"(addr));
}
__device__ __forceinline__ void mma_bf16(float* c, const uint32_t* a, const uint32_t* b){
    asm volatile("mma.sync.aligned.m16n8k16.row.col.f32.bf16.bf16.f32 "
        "{%0,%1,%2,%3}, {%4,%5,%6,%7}, {%8,%9}, {%0,%1,%2,%3};"
        : "+f"(c[0]), "+f"(c[1]), "+f"(c[2]), "+f"(c[3])
        : "r"(a[0]), "r"(a[1]), "r"(a[2]), "r"(a[3]), "r"(b[0]), "r"(b[1]));
}

// ---------------- HMMA bf16x3 GEMM: C = A * op(B), 128x128 tile, BK=32 ----------------
// A: [M,K] row-major. B: TRANS_B ? [N,K] : [K,N]. C: [M,N] fp32.
// 256 threads = 8 warps (4 m-warps x 2 n-warps); warp tile 32m x 64n.
// smem layouts (bf16): A[128][40] padded; B trans: [128 n][40 k]; B non-trans: [32 k][136 n].
#define A_PITCH 40      // elems (80 B)
#define BN_PITCH 40
#define BK_PITCH 136    // elems (272 B)

template<bool TRANS_B, bool CSKIP, bool CKLIM>
__global__ void __launch_bounds__(256) tgemm_kernel(
    const float* __restrict__ A, const float* __restrict__ Bm, float* __restrict__ C,
    int M, int N, int K, int lda, int ldb, int ldc,
    int divA, long long sA1, long long sA2,
    int divB, long long sB1, long long sB2,
    int divC, long long sC1, long long sC2)
{
    constexpr int BM = 128, BN = 128, BK = 32;
    int m0 = blockIdx.y*BM, n0 = blockIdx.x*BN;
    if (CSKIP && n0 >= m0 + BM) return;
    int z = blockIdx.z;
    A  += (long long)(z/divA)*sA1 + (long long)(z%divA)*sA2;
    Bm += (long long)(z/divB)*sB1 + (long long)(z%divB)*sB2;
    C  += (long long)(z/divC)*sC1 + (long long)(z%divC)*sC2;
    int kEnd = CKLIM ? min(K, m0 + BM) : K;
    int nk = kEnd / BK;

    __shared__ __align__(128) char smem_raw[40960];
    uint32_t sbase = smem_u32(smem_raw);
    uint32_t sAh = sbase;
    uint32_t sAl = sbase + 10240;
    uint32_t sBh = sbase + 20480;
    uint32_t sBl = sBh + (TRANS_B ? 10240 : 8704);

    int tid  = threadIdx.x;
    int lane = tid & 31, wid = tid >> 5;
    int wm = wid & 3, wn = wid >> 2;

    // gmem load mapping
    int rA  = tid >> 3;            // 0..31 (row group for A / trans-B)
    int kgA = (tid & 7) * 4;       // 0..28
    int kB  = tid >> 5;            // 0..7   (!TRANS_B)
    int nB  = (tid & 31) * 4;      // 0..124

    float acc[2][8][4];
    #pragma unroll
    for (int i=0;i<2;i++)
        #pragma unroll
        for (int j=0;j<8;j++)
            #pragma unroll
            for (int q=0;q<4;q++) acc[i][j][q] = 0.f;

    float4 ra[4], rb[4];

    // ---- prologue: load chunk 0 into regs
    {
        const float* pA = A + (size_t)(m0 + rA)*lda + kgA;
        #pragma unroll
        for (int i=0;i<4;i++) ra[i] = *reinterpret_cast<const float4*>(pA + (size_t)(32*i)*lda);
        if (TRANS_B) {
            const float* pB = Bm + (size_t)(n0 + rA)*ldb + kgA;
            #pragma unroll
            for (int i=0;i<4;i++) {
                if (n0 + rA + 32*i < N) rb[i] = *reinterpret_cast<const float4*>(pB + (size_t)(32*i)*ldb);
                else                    rb[i] = make_float4(0.f,0.f,0.f,0.f);
            }
        } else {
            const float* pB = Bm + (size_t)kB*ldb + n0 + nB;
            #pragma unroll
            for (int i=0;i<4;i++) rb[i] = *reinterpret_cast<const float4*>(pB + (size_t)(8*i)*ldb);
        }
    }

    // ldmatrix address bases (per thread)
    uint32_t aOff = (uint32_t)((wm*32 + (lane & 15))*A_PITCH*2 + ((lane >> 4)*8)*2);
    uint32_t bOffT = (uint32_t)((wn*64 + (lane & 7))*BN_PITCH*2 + (((lane >> 3) & 1)*8)*2);
    uint32_t bOffN = (uint32_t)((lane & 15)*BK_PITCH*2 + (wn*64)*2);

    for (int kb = 0; kb < nk; kb++) {
        // ---- convert + STS current chunk
        #pragma unroll
        for (int i=0;i<4;i++) {
            uint32_t h0,l0,h1,l1;
            split2(ra[i].x, ra[i].y, h0, l0);
            split2(ra[i].z, ra[i].w, h1, l1);
            uint32_t off = (uint32_t)((rA + 32*i)*A_PITCH*2 + kgA*2);
            asm volatile("st.shared.v2.b32 [%0], {%1,%2};" :: "r"(sAh+off), "r"(h0), "r"(h1));
            asm volatile("st.shared.v2.b32 [%0], {%1,%2};" :: "r"(sAl+off), "r"(l0), "r"(l1));
        }
        if (TRANS_B) {
            #pragma unroll
            for (int i=0;i<4;i++) {
                uint32_t h0,l0,h1,l1;
                split2(rb[i].x, rb[i].y, h0, l0);
                split2(rb[i].z, rb[i].w, h1, l1);
                uint32_t off = (uint32_t)((rA + 32*i)*BN_PITCH*2 + kgA*2);
                asm volatile("st.shared.v2.b32 [%0], {%1,%2};" :: "r"(sBh+off), "r"(h0), "r"(h1));
                asm volatile("st.shared.v2.b32 [%0], {%1,%2};" :: "r"(sBl+off), "r"(l0), "r"(l1));
            }
        } else {
            #pragma unroll
            for (int i=0;i<4;i++) {
                uint32_t h0,l0,h1,l1;
                split2(rb[i].x, rb[i].y, h0, l0);
                split2(rb[i].z, rb[i].w, h1, l1);
                uint32_t off = (uint32_t)((kB + 8*i)*BK_PITCH*2 + nB*2);
                asm volatile("st.shared.v2.b32 [%0], {%1,%2};" :: "r"(sBh+off), "r"(h0), "r"(h1));
                asm volatile("st.shared.v2.b32 [%0], {%1,%2};" :: "r"(sBl+off), "r"(l0), "r"(l1));
            }
        }
        __syncthreads();

        // ---- prefetch next chunk into regs (LDG latency hidden under mma)
        if (kb + 1 < nk) {
            int k0 = (kb+1)*BK;
            const float* pA = A + (size_t)(m0 + rA)*lda + k0 + kgA;
            #pragma unroll
            for (int i=0;i<4;i++) ra[i] = *reinterpret_cast<const float4*>(pA + (size_t)(32*i)*lda);
            if (TRANS_B) {
                const float* pB = Bm + (size_t)(n0 + rA)*ldb + k0 + kgA;
                #pragma unroll
                for (int i=0;i<4;i++) {
                    if (n0 + rA + 32*i < N) rb[i] = *reinterpret_cast<const float4*>(pB + (size_t)(32*i)*ldb);
                    else                    rb[i] = make_float4(0.f,0.f,0.f,0.f);
                }
            } else {
                const float* pB = Bm + (size_t)(k0 + kB)*ldb + n0 + nB;
                #pragma unroll
                for (int i=0;i<4;i++) rb[i] = *reinterpret_cast<const float4*>(pB + (size_t)(8*i)*ldb);
            }
        }

        // ---- tensor compute on smem chunk
        #pragma unroll
        for (int ks = 0; ks < 2; ks++) {
            uint32_t ah[2][4], al[2][4];
            #pragma unroll
            for (int mt = 0; mt < 2; mt++) {
                ldm_x4(ah[mt], sAh + aOff + (uint32_t)(mt*16*A_PITCH*2 + ks*32));
                ldm_x4(al[mt], sAl + aOff + (uint32_t)(mt*16*A_PITCH*2 + ks*32));
            }
            #pragma unroll
            for (int nt = 0; nt < 8; nt++) {
                uint32_t bh[2], bl[2];
                if (TRANS_B) {
                    ldm_x2(bh, sBh + bOffT + (uint32_t)(nt*8*BN_PITCH*2 + ks*32));
                    ldm_x2(bl, sBl + bOffT + (uint32_t)(nt*8*BN_PITCH*2 + ks*32));
                } else {
                    ldm_x2t(bh, sBh + bOffN + (uint32_t)(ks*16*BK_PITCH*2 + nt*16));
                    ldm_x2t(bl, sBl + bOffN + (uint32_t)(ks*16*BK_PITCH*2 + nt*16));
                }
                #pragma unroll
                for (int mt = 0; mt < 2; mt++) {
                    mma_bf16(acc[mt][nt], ah[mt], bh);
                    mma_bf16(acc[mt][nt], ah[mt], bl);
                    mma_bf16(acc[mt][nt], al[mt], bh);
                }
            }
        }
        __syncthreads();
    }

    // ---- epilogue: acc -> C
    int mwarp = m0 + wm*32;
    int nwarp = n0 + wn*64;
    int rlo = lane >> 2;            // 0..7
    int cpair = (lane & 3)*2;       // 0,2,4,6
    #pragma unroll
    for (int mt = 0; mt < 2; mt++) {
        #pragma unroll
        for (int nt = 0; nt < 8; nt++) {
            int c = nwarp + nt*8 + cpair;
            if (c < N) {
                size_t r0 = (size_t)(mwarp + mt*16 + rlo);
                float2 v0 = make_float2(acc[mt][nt][0], acc[mt][nt][1]);
                float2 v1 = make_float2(acc[mt][nt][2], acc[mt][nt][3]);
                *reinterpret_cast<float2*>(C + r0*ldc + c)       = v0;
                *reinterpret_cast<float2*>(C + (r0+8)*ldc + c)   = v1;
            }
        }
    }
}

// ---------------- RoPE tables ----------------
__global__ void rope_init_kernel() {
    int idx = blockIdx.x*blockDim.x + threadIdx.x;
    if (idx >= S_*(ROPE_/2)) return;
    int t = idx / (ROPE_/2);
    int i = idx % (ROPE_/2);
    double freq = pow(10000.0, -(double)(2*i)/(double)ROPE_);
    double ang  = (double)t * freq;
    g_cos[idx] = (float)cos(ang);
    g_sin[idx] = (float)sin(ang);
}

// ---------------- rmsnorm(kv_lat) + RoPE(k_pe, q_pe) ----------------
__global__ void __launch_bounds__(256) prep_kernel(const float* __restrict__ kv_norm_w) {
    int bs  = blockIdx.x;
    int s   = bs % S_;
    int tid = threadIdx.x;
    const float* kv = g_kv_raw + (size_t)bs*DQK_;
    float*       kf = g_kfull  + (size_t)bs*DQK_;

    __shared__ float red[256];
    float ss = 0.f;
    for (int j = tid; j < KVR_; j += 256) { float v = kv[j]; ss += v*v; }
    red[tid] = ss; __syncthreads();
    #pragma unroll
    for (int o = 128; o > 0; o >>= 1) {
        if (tid < o) red[tid] += red[tid+o];
        __syncthreads();
    }
    float inv = 1.f / sqrtf(red[0] / (float)KVR_ + 1e-6f);

    for (int j = tid; j < KVR_; j += 256)
        kf[j] = kv[j] * inv * kv_norm_w[j];

    for (int i = tid; i < ROPE_/2; i += 256) {
        float x0 = kv[KVR_ + 2*i], x1 = kv[KVR_ + 2*i + 1];
        float c = g_cos[s*(ROPE_/2)+i], sn = g_sin[s*(ROPE_/2)+i];
        kf[KVR_ + 2*i]     = x0*c  - x1*sn;
        kf[KVR_ + 2*i + 1] = x0*sn + x1*c;
    }

    const float* qr = g_q_raw + (size_t)bs*NQ_;
    float*       qf = g_qfull + (size_t)bs*H_*DQK_;
    for (int idx = tid; idx < H_*(ROPE_/2); idx += 256) {
        int h = idx >> 5, i = idx & 31;
        float x0 = qr[h*QKH_ + NOPE_ + 2*i], x1 = qr[h*QKH_ + NOPE_ + 2*i + 1];
        float c = g_cos[s*(ROPE_/2)+i], sn = g_sin[s*(ROPE_/2)+i];
        qf[h*DQK_ + KVR_ + 2*i]     = x0*c  - x1*sn;
        qf[h*DQK_ + KVR_ + 2*i + 1] = x0*sn + x1*c;
    }
}

// ---------------- causal softmax, in-place on g_scores ----------------
__global__ void __launch_bounds__(256) softmax_kernel() {
    int s = blockIdx.x;
    int z = blockIdx.y;
    float* row = g_scores + ((size_t)z*S_ + s)*S_;
    int n = s + 1;
    int tid = threadIdx.x;
    __shared__ float red[256];

    float mx = -3.4e38f;
    for (int t = tid; t < n; t += 256) mx = fmaxf(mx, row[t]);
    red[tid] = mx; __syncthreads();
    #pragma unroll
    for (int o = 128; o > 0; o >>= 1) {
        if (tid < o) red[tid] = fmaxf(red[tid], red[tid+o]);
        __syncthreads();
    }
    mx = red[0];
    __syncthreads();

    float sum = 0.f;
    for (int t = tid; t < n; t += 256) {
        float e = expf((row[t] - mx) * SCALE_F);
        row[t] = e;
        sum += e;
    }
    red[tid] = sum; __syncthreads();
    #pragma unroll
    for (int o = 128; o > 0; o >>= 1) {
        if (tid < o) red[tid] += red[tid+o];
        __syncthreads();
    }
    float inv = 1.f / red[0];

    for (int t = tid; t < n; t += 256) row[t] *= inv;
    for (int t = n + tid; t < S_; t += 256) row[t] = 0.f;
}

// ---------------- launch ----------------
extern "C" void kernel_launch(void* const* d_in, const int* in_sizes, int n_in,
                              void* d_out, int out_size) {
    const float* x      = (const float*)d_in[0];
    const float* wq     = (const float*)d_in[1];
    const float* wkv_a  = (const float*)d_in[2];
    const float* wkv_b  = (const float*)d_in[3];
    const float* wo     = (const float*)d_in[4];
    const float* kvw    = (const float*)d_in[5];
    float* out = (float*)d_out;

    float *q_raw, *kv_raw, *kfull, *qfull, *scores, *outlat, *outv;
    cudaGetSymbolAddress((void**)&q_raw,  g_q_raw);
    cudaGetSymbolAddress((void**)&kv_raw, g_kv_raw);
    cudaGetSymbolAddress((void**)&kfull,  g_kfull);
    cudaGetSymbolAddress((void**)&qfull,  g_qfull);
    cudaGetSymbolAddress((void**)&scores, g_scores);
    cudaGetSymbolAddress((void**)&outlat, g_outlat);
    cudaGetSymbolAddress((void**)&outv,   g_outv);

    // 1) q_raw = x @ wq^T       [4096,3072]
    tgemm_kernel<true,false,false><<<dim3(NQ_/128, BS_/128, 1), 256>>>(
        x, wq, q_raw, BS_, NQ_, DIM_, DIM_, DIM_, NQ_,
        1,0,0, 1,0,0, 1,0,0);

    // 2) kv_raw = x @ wkv_a^T   [4096,576]  (ragged N, guarded)
    tgemm_kernel<true,false,false><<<dim3((DQK_+127)/128, BS_/128, 1), 256>>>(
        x, wkv_a, kv_raw, BS_, DQK_, DIM_, DIM_, DIM_, DQK_,
        1,0,0, 1,0,0, 1,0,0);

    // 3) RoPE tables
    rope_init_kernel<<<(S_*(ROPE_/2)+255)/256, 256>>>();

    // 4) rmsnorm + rope
    prep_kernel<<<BS_, 256>>>(kvw);

    // 5) q_lat[h] = q_nope[:,h] @ wkv_b_h[h,:128,:]   (z = head, B non-trans)
    tgemm_kernel<false,false,false><<<dim3(KVR_/128, BS_/128, H_), 256>>>(
        q_raw, wkv_b, qfull, BS_, KVR_, NOPE_, NQ_, KVR_, H_*DQK_,
        1, QKH_, 0,
        1, (long long)(NOPE_+VD_)*KVR_, 0,
        1, DQK_, 0);

    // 6) scores[b,h] = q_full @ k_full^T  (z = b*H+h), causal tile skip
    tgemm_kernel<true,true,false><<<dim3(S_/128, S_/128, B_*H_), 256>>>(
        qfull, kfull, scores, S_, S_, DQK_, H_*DQK_, DQK_, S_,
        H_, (long long)S_*H_*DQK_, DQK_,
        H_, (long long)S_*DQK_, 0,
        1, (long long)S_*S_, 0);

    // 7) causal softmax in-place
    softmax_kernel<<<dim3(S_, B_*H_), 256>>>();

    // 8) out_lat = attn @ kv_cache   (causal K-limit, B non-trans)
    tgemm_kernel<false,false,true><<<dim3(KVR_/128, S_/128, B_*H_), 256>>>(
        scores, kfull, outlat, S_, KVR_, S_, S_, DQK_, H_*KVR_,
        1, (long long)S_*S_, 0,
        H_, (long long)S_*DQK_, 0,
        H_, (long long)S_*H_*KVR_, KVR_);

    // 9) outv[:,h] = out_lat[:,h,:] @ wkv_b_h[h,128:,:]^T  (z = head)
    tgemm_kernel<true,false,false><<<dim3(VD_/128, BS_/128, H_), 256>>>(
        outlat, wkv_b + (size_t)NOPE_*KVR_, outv, BS_, VD_, KVR_, H_*KVR_, KVR_, H_*VD_,
        1, KVR_, 0,
        1, (long long)(NOPE_+VD_)*KVR_, 0,
        1, VD_, 0);

    // 10) out = outv @ wo^T     [4096,2048]
    tgemm_kernel<true,false,false><<<dim3(DIM_/128, BS_/128, 1), 256>>>(
        outv, wo, out, BS_, DIM_, H_*VD_, H_*VD_, H_*VD_, DIM_,
        1,0,0, 1,0,0, 1,0,0);
}